// round 1
// baseline (speedup 1.0000x reference)
#include <cuda_runtime.h>
#include <cstdint>

#define TOK_B 65536
#define IN_D  1280
#define NEXP  8
#define H1D   256
#define H2D   128
#define BM    128
#define NTHR  256

// smem strides (in floats) chosen for conflict-free mma fragment LDS:
//  A-operand buffers need stride % 32 == 4; B-operand buffers need stride % 32 == 8.
#define XS_ST 36
#define WS_ST 264
#define W2_ST 136
#define H1_ST 260

#define XS_OFF  0
#define WS_OFF  (BM * XS_ST)                 // 4608
#define H1_OFF  (WS_OFF + 32 * WS_ST)        // 13056
#define W3_OFF  (H1_OFF + BM * H1_ST)        // 46336
#define EO_OFF  (W3_OFF + H2D)               // 46464
#define EOP_OFF (EO_OFF + BM * NEXP)         // 47488
#define SM_FLOATS (EOP_OFF + BM * 4)         // 48000
#define SM_BYTES  (SM_FLOATS * 4)            // 192000

__device__ __forceinline__ float tf32r(float f) {
    uint32_t u;
    asm("cvt.rna.tf32.f32 %0, %1;" : "=r"(u) : "f"(f));
    return __uint_as_float(u);
}

__device__ __forceinline__ void mma8(float* c, const uint32_t* a, const uint32_t* b) {
    asm volatile(
        "mma.sync.aligned.m16n8k8.row.col.f32.tf32.tf32.f32 "
        "{%0,%1,%2,%3}, {%4,%5,%6,%7}, {%8,%9}, {%0,%1,%2,%3};\n"
        : "+f"(c[0]), "+f"(c[1]), "+f"(c[2]), "+f"(c[3])
        : "r"(a[0]), "r"(a[1]), "r"(a[2]), "r"(a[3]),
          "r"(b[0]), "r"(b[1]));
}

__global__ void __launch_bounds__(NTHR, 1)
moe_fused(const float* __restrict__ x,  const float* __restrict__ W1,
          const float* __restrict__ b1, const float* __restrict__ W2,
          const float* __restrict__ b2, const float* __restrict__ W3,
          const float* __restrict__ b3, const float* __restrict__ Wg,
          const float* __restrict__ bg, float* __restrict__ out, int write_gate)
{
    extern __shared__ float sm[];
    float* xs  = sm + XS_OFF;   // [128][36]  A tile (x, tf32)
    float* ws  = sm + WS_OFF;   // [32][264] B tile (W1) / [32][136] (W2)
    float* h1s = sm + H1_OFF;   // [128][260] h1 (tf32) / gate partials
    float* w3s = sm + W3_OFF;   // [128]
    float* eos = sm + EO_OFF;   // [128][8] expert outputs
    float* eop = sm + EOP_OFF;  // [128][4] per-warp partials

    const int tid  = threadIdx.x;
    const int lane = tid & 31, warp = tid >> 5;
    const int g = lane >> 2, t = lane & 3;       // mma group / thread-in-group
    const int wm = warp >> 2, wn = warp & 3;     // 2 x 4 warp grid
    const int row0 = blockIdx.x * BM;

    const int xr = tid >> 3;                     // x loader: row-in-pass
    const int xc = (tid & 7) * 4;                // x loader: col (float4)

    for (int e = 0; e < NEXP; ++e) {
        // ================= GEMM1: h1 = relu(x @ W1[e] + b1[e]) =================
        const float* w1g = W1 + (size_t)e * IN_D * H1D;

        float acc1[4][8][4];
        #pragma unroll
        for (int mt = 0; mt < 4; ++mt)
            #pragma unroll
            for (int nt = 0; nt < 8; ++nt)
                #pragma unroll
                for (int i = 0; i < 4; ++i) acc1[mt][nt][i] = 0.f;

        float4 av[4], wv[8];
        #pragma unroll
        for (int p = 0; p < 4; ++p)
            av[p] = *(const float4*)(x + (size_t)(row0 + p * 32 + xr) * IN_D + xc);
        #pragma unroll
        for (int p = 0; p < 8; ++p) {
            int i2 = p * NTHR + tid; int k = i2 >> 6; int c = (i2 & 63) * 4;
            wv[p] = *(const float4*)(w1g + (size_t)k * H1D + c);
        }

        for (int kt = 0; kt < IN_D / 32; ++kt) {
            __syncthreads();
            #pragma unroll
            for (int p = 0; p < 4; ++p) {
                float4 v = av[p];
                v.x = tf32r(v.x); v.y = tf32r(v.y); v.z = tf32r(v.z); v.w = tf32r(v.w);
                *(float4*)(xs + (p * 32 + xr) * XS_ST + xc) = v;
            }
            #pragma unroll
            for (int p = 0; p < 8; ++p) {
                int i2 = p * NTHR + tid; int k = i2 >> 6; int c = (i2 & 63) * 4;
                float4 v = wv[p];
                v.x = tf32r(v.x); v.y = tf32r(v.y); v.z = tf32r(v.z); v.w = tf32r(v.w);
                *(float4*)(ws + k * WS_ST + c) = v;
            }
            __syncthreads();

            if (kt + 1 < IN_D / 32) {               // prefetch next tile into regs
                int k0 = (kt + 1) * 32;
                #pragma unroll
                for (int p = 0; p < 4; ++p)
                    av[p] = *(const float4*)(x + (size_t)(row0 + p * 32 + xr) * IN_D + k0 + xc);
                #pragma unroll
                for (int p = 0; p < 8; ++p) {
                    int i2 = p * NTHR + tid; int k = i2 >> 6; int c = (i2 & 63) * 4;
                    wv[p] = *(const float4*)(w1g + (size_t)(k0 + k) * H1D + c);
                }
            }

            #pragma unroll
            for (int ks = 0; ks < 4; ++ks) {
                const int kk = ks * 8 + t;
                uint32_t af[4][4];
                #pragma unroll
                for (int mt = 0; mt < 4; ++mt) {
                    int r = wm * 64 + mt * 16 + g;
                    af[mt][0] = __float_as_uint(xs[r * XS_ST + kk]);
                    af[mt][1] = __float_as_uint(xs[(r + 8) * XS_ST + kk]);
                    af[mt][2] = __float_as_uint(xs[r * XS_ST + kk + 4]);
                    af[mt][3] = __float_as_uint(xs[(r + 8) * XS_ST + kk + 4]);
                }
                uint32_t bf[8][2];
                #pragma unroll
                for (int nt = 0; nt < 8; ++nt) {
                    int n = wn * 64 + nt * 8 + g;
                    bf[nt][0] = __float_as_uint(ws[kk * WS_ST + n]);
                    bf[nt][1] = __float_as_uint(ws[(kk + 4) * WS_ST + n]);
                }
                #pragma unroll
                for (int mt = 0; mt < 4; ++mt)
                    #pragma unroll
                    for (int nt = 0; nt < 8; ++nt)
                        mma8(acc1[mt][nt], af[mt], bf[nt]);
            }
        }

        // epilogue: bias + relu, tf32-round into smem h1
        const float* b1e = b1 + e * H1D;
        #pragma unroll
        for (int nt = 0; nt < 8; ++nt) {
            int c = wn * 64 + nt * 8 + 2 * t;
            float bb0 = b1e[c], bb1 = b1e[c + 1];
            #pragma unroll
            for (int mt = 0; mt < 4; ++mt) {
                int r = wm * 64 + mt * 16 + g;
                h1s[r * H1_ST + c]           = tf32r(fmaxf(acc1[mt][nt][0] + bb0, 0.f));
                h1s[r * H1_ST + c + 1]       = tf32r(fmaxf(acc1[mt][nt][1] + bb1, 0.f));
                h1s[(r + 8) * H1_ST + c]     = tf32r(fmaxf(acc1[mt][nt][2] + bb0, 0.f));
                h1s[(r + 8) * H1_ST + c + 1] = tf32r(fmaxf(acc1[mt][nt][3] + bb1, 0.f));
            }
        }
        if (tid < H2D) w3s[tid] = W3[e * H2D + tid];
        __syncthreads();

        // ================= GEMM2: h2 = relu(h1 @ W2[e] + b2[e]); eo = h2 . W3[e] =================
        float acc2[4][4][4];
        #pragma unroll
        for (int mt = 0; mt < 4; ++mt)
            #pragma unroll
            for (int nt = 0; nt < 4; ++nt)
                #pragma unroll
                for (int i = 0; i < 4; ++i) acc2[mt][nt][i] = 0.f;

        const float* w2g = W2 + (size_t)e * H1D * H2D;
        float4 wv2[4];
        #pragma unroll
        for (int p = 0; p < 4; ++p) {
            int i2 = p * NTHR + tid; int k = i2 >> 5; int c = (i2 & 31) * 4;
            wv2[p] = *(const float4*)(w2g + (size_t)k * H2D + c);
        }

        for (int kc = 0; kc < H1D / 32; ++kc) {
            __syncthreads();
            #pragma unroll
            for (int p = 0; p < 4; ++p) {
                int i2 = p * NTHR + tid; int k = i2 >> 5; int c = (i2 & 31) * 4;
                float4 v = wv2[p];
                v.x = tf32r(v.x); v.y = tf32r(v.y); v.z = tf32r(v.z); v.w = tf32r(v.w);
                *(float4*)(ws + k * W2_ST + c) = v;
            }
            __syncthreads();
            if (kc + 1 < H1D / 32) {
                int k0 = (kc + 1) * 32;
                #pragma unroll
                for (int p = 0; p < 4; ++p) {
                    int i2 = p * NTHR + tid; int k = i2 >> 5; int c = (i2 & 31) * 4;
                    wv2[p] = *(const float4*)(w2g + (size_t)(k0 + k) * H2D + c);
                }
            }
            #pragma unroll
            for (int ks = 0; ks < 4; ++ks) {
                const int kl = ks * 8 + t;
                const int kk = kc * 32 + kl;
                uint32_t af[4][4];
                #pragma unroll
                for (int mt = 0; mt < 4; ++mt) {
                    int r = wm * 64 + mt * 16 + g;
                    af[mt][0] = __float_as_uint(h1s[r * H1_ST + kk]);
                    af[mt][1] = __float_as_uint(h1s[(r + 8) * H1_ST + kk]);
                    af[mt][2] = __float_as_uint(h1s[r * H1_ST + kk + 4]);
                    af[mt][3] = __float_as_uint(h1s[(r + 8) * H1_ST + kk + 4]);
                }
                uint32_t bf[4][2];
                #pragma unroll
                for (int nt = 0; nt < 4; ++nt) {
                    int n = wn * 32 + nt * 8 + g;
                    bf[nt][0] = __float_as_uint(ws[kl * W2_ST + n]);
                    bf[nt][1] = __float_as_uint(ws[(kl + 4) * W2_ST + n]);
                }
                #pragma unroll
                for (int mt = 0; mt < 4; ++mt)
                    #pragma unroll
                    for (int nt = 0; nt < 4; ++nt)
                        mma8(acc2[mt][nt], af[mt], bf[nt]);
            }
        }

        // epilogue: relu + fold h2 . W3 directly from accumulators
        const float* b2e = b2 + e * H2D;
        float w30[4], w31[4], bb0[4], bb1[4];
        #pragma unroll
        for (int nt = 0; nt < 4; ++nt) {
            int c = wn * 32 + nt * 8 + 2 * t;
            w30[nt] = w3s[c];     w31[nt] = w3s[c + 1];
            bb0[nt] = b2e[c];     bb1[nt] = b2e[c + 1];
        }
        #pragma unroll
        for (int mt = 0; mt < 4; ++mt) {
            int r = wm * 64 + mt * 16 + g;
            float s0 = 0.f, s1 = 0.f;
            #pragma unroll
            for (int nt = 0; nt < 4; ++nt) {
                s0 += fmaxf(acc2[mt][nt][0] + bb0[nt], 0.f) * w30[nt]
                    + fmaxf(acc2[mt][nt][1] + bb1[nt], 0.f) * w31[nt];
                s1 += fmaxf(acc2[mt][nt][2] + bb0[nt], 0.f) * w30[nt]
                    + fmaxf(acc2[mt][nt][3] + bb1[nt], 0.f) * w31[nt];
            }
            s0 += __shfl_xor_sync(0xffffffffu, s0, 1);
            s0 += __shfl_xor_sync(0xffffffffu, s0, 2);
            s1 += __shfl_xor_sync(0xffffffffu, s1, 1);
            s1 += __shfl_xor_sync(0xffffffffu, s1, 2);
            if (t == 0) {
                eop[r * 4 + wn]       = s0;
                eop[(r + 8) * 4 + wn] = s1;
            }
        }
        __syncthreads();
        if (tid < BM) {
            eos[tid * NEXP + e] = eop[tid * 4 + 0] + eop[tid * 4 + 1]
                                + eop[tid * 4 + 2] + eop[tid * 4 + 3];
        }
    }
    __syncthreads();

    // ================= gate: softmax(x @ Wg + bg); predictions =================
    {
        int token = tid & 127, half = tid >> 7;
        const float* xrow = x + (size_t)(row0 + token) * IN_D + half * 640;
        const float* wg = Wg + (size_t)half * 640 * NEXP;
        float l[8];
        #pragma unroll
        for (int e2 = 0; e2 < 8; ++e2) l[e2] = 0.f;
        #pragma unroll 4
        for (int k = 0; k < 640; ++k) {
            float xv = xrow[k];
            float4 wa = *(const float4*)(wg + k * 8);
            float4 wb = *(const float4*)(wg + k * 8 + 4);
            l[0] += xv * wa.x; l[1] += xv * wa.y; l[2] += xv * wa.z; l[3] += xv * wa.w;
            l[4] += xv * wb.x; l[5] += xv * wb.y; l[6] += xv * wb.z; l[7] += xv * wb.w;
        }
        float* gp = h1s;  // reuse (free now)
        #pragma unroll
        for (int e2 = 0; e2 < 8; ++e2) gp[(token * 2 + half) * 8 + e2] = l[e2];
    }
    __syncthreads();
    if (tid < BM) {
        const float* gp = h1s;
        float lg[8];
        #pragma unroll
        for (int e2 = 0; e2 < 8; ++e2)
            lg[e2] = gp[tid * 16 + e2] + gp[tid * 16 + 8 + e2] + bg[e2];
        float m = lg[0];
        #pragma unroll
        for (int e2 = 1; e2 < 8; ++e2) m = fmaxf(m, lg[e2]);
        float pe[8], s = 0.f;
        #pragma unroll
        for (int e2 = 0; e2 < 8; ++e2) { pe[e2] = expf(lg[e2] - m); s += pe[e2]; }
        float inv = 1.0f / s;
        float pred = 0.f;
        #pragma unroll
        for (int e2 = 0; e2 < 8; ++e2) {
            float gv = pe[e2] * inv;
            pred += (eos[tid * NEXP + e2] + b3[e2]) * gv;
            if (write_gate) out[TOK_B + (size_t)(row0 + tid) * NEXP + e2] = gv;
        }
        out[row0 + tid] = pred;
    }
}

extern "C" void kernel_launch(void* const* d_in, const int* in_sizes, int n_in,
                              void* d_out, int out_size) {
    const float* x  = (const float*)d_in[0];
    const float* W1 = (const float*)d_in[1];
    const float* b1 = (const float*)d_in[2];
    const float* W2 = (const float*)d_in[3];
    const float* b2 = (const float*)d_in[4];
    const float* W3 = (const float*)d_in[5];
    const float* b3 = (const float*)d_in[6];
    const float* Wg = (const float*)d_in[7];
    const float* bg = (const float*)d_in[8];
    float* out = (float*)d_out;
    int write_gate = (out_size >= TOK_B * (NEXP + 1)) ? 1 : 0;

    cudaFuncSetAttribute(moe_fused, cudaFuncAttributeMaxDynamicSharedMemorySize, SM_BYTES);
    moe_fused<<<TOK_B / BM, NTHR, SM_BYTES>>>(x, W1, b1, W2, b2, W3, b3, Wg, bg, out, write_gate);
}

// round 4
// speedup vs baseline: 1.0007x; 1.0007x over previous
#include <cuda_runtime.h>
#include <cstdint>

#define TOK_B 65536
#define IN_D  1280
#define NEXP  8
#define H1D   256
#define H2D   128
#define BM    128
#define NTHR  256

// smem strides (in floats) chosen for conflict-free mma fragment LDS:
//  A-operand buffers need stride % 32 == 4; B-operand buffers need stride % 32 == 8.
#define XS_ST 36
#define WS_ST 264
#define W2_ST 136
#define H1_ST 260

#define XS_OFF  0
#define WS_OFF  (BM * XS_ST)                 // 4608
#define H1_OFF  (WS_OFF + 32 * WS_ST)        // 13056
#define W3_OFF  (H1_OFF + BM * H1_ST)        // 46336
#define EO_OFF  (W3_OFF + H2D)               // 46464
#define EOP_OFF (EO_OFF + BM * NEXP)         // 47488
#define SM_FLOATS (EOP_OFF + BM * 4)         // 48000
#define SM_BYTES  (SM_FLOATS * 4)            // 192000

__device__ __forceinline__ float tf32r(float f) {
    uint32_t u;
    asm("cvt.rna.tf32.f32 %0, %1;" : "=r"(u) : "f"(f));
    return __uint_as_float(u);
}

__device__ __forceinline__ void mma8(float* c, const uint32_t* a, const uint32_t* b) {
    asm volatile(
        "mma.sync.aligned.m16n8k8.row.col.f32.tf32.tf32.f32 "
        "{%0,%1,%2,%3}, {%4,%5,%6,%7}, {%8,%9}, {%0,%1,%2,%3};\n"
        : "+f"(c[0]), "+f"(c[1]), "+f"(c[2]), "+f"(c[3])
        : "r"(a[0]), "r"(a[1]), "r"(a[2]), "r"(a[3]),
          "r"(b[0]), "r"(b[1]));
}

__global__ void __launch_bounds__(NTHR, 1)
moe_fused(const float* __restrict__ x,  const float* __restrict__ W1,
          const float* __restrict__ b1, const float* __restrict__ W2,
          const float* __restrict__ b2, const float* __restrict__ W3,
          const float* __restrict__ b3, const float* __restrict__ Wg,
          const float* __restrict__ bg, float* __restrict__ out, int write_gate)
{
    extern __shared__ float sm[];
    float* xs  = sm + XS_OFF;   // [128][36]  A tile (x, tf32)
    float* ws  = sm + WS_OFF;   // [32][264] B tile (W1) / [32][136] (W2)
    float* h1s = sm + H1_OFF;   // [128][260] h1 (tf32) / gate partials
    float* w3s = sm + W3_OFF;   // [128]
    float* eos = sm + EO_OFF;   // [128][8] expert outputs
    float* eop = sm + EOP_OFF;  // [128][4] per-warp partials

    const int tid  = threadIdx.x;
    const int lane = tid & 31, warp = tid >> 5;
    const int g = lane >> 2, t = lane & 3;       // mma group / thread-in-group
    const int wm = warp >> 2, wn = warp & 3;     // 2 x 4 warp grid
    const int row0 = blockIdx.x * BM;

    const int xr = tid >> 3;                     // x loader: row-in-pass
    const int xc = (tid & 7) * 4;                // x loader: col (float4)

    for (int e = 0; e < NEXP; ++e) {
        // ================= GEMM1: h1 = relu(x @ W1[e] + b1[e]) =================
        const float* w1g = W1 + (size_t)e * IN_D * H1D;

        float acc1[4][8][4];
        #pragma unroll
        for (int mt = 0; mt < 4; ++mt)
            #pragma unroll
            for (int nt = 0; nt < 8; ++nt)
                #pragma unroll
                for (int i = 0; i < 4; ++i) acc1[mt][nt][i] = 0.f;

        float4 av[4], wv[8];
        #pragma unroll
        for (int p = 0; p < 4; ++p)
            av[p] = *(const float4*)(x + (size_t)(row0 + p * 32 + xr) * IN_D + xc);
        #pragma unroll
        for (int p = 0; p < 8; ++p) {
            int i2 = p * NTHR + tid; int k = i2 >> 6; int c = (i2 & 63) * 4;
            wv[p] = *(const float4*)(w1g + (size_t)k * H1D + c);
        }

        for (int kt = 0; kt < IN_D / 32; ++kt) {
            __syncthreads();
            #pragma unroll
            for (int p = 0; p < 4; ++p) {
                float4 v = av[p];
                v.x = tf32r(v.x); v.y = tf32r(v.y); v.z = tf32r(v.z); v.w = tf32r(v.w);
                *(float4*)(xs + (p * 32 + xr) * XS_ST + xc) = v;
            }
            #pragma unroll
            for (int p = 0; p < 8; ++p) {
                int i2 = p * NTHR + tid; int k = i2 >> 6; int c = (i2 & 63) * 4;
                float4 v = wv[p];
                v.x = tf32r(v.x); v.y = tf32r(v.y); v.z = tf32r(v.z); v.w = tf32r(v.w);
                *(float4*)(ws + k * WS_ST + c) = v;
            }
            __syncthreads();

            if (kt + 1 < IN_D / 32) {               // prefetch next tile into regs
                int k0 = (kt + 1) * 32;
                #pragma unroll
                for (int p = 0; p < 4; ++p)
                    av[p] = *(const float4*)(x + (size_t)(row0 + p * 32 + xr) * IN_D + k0 + xc);
                #pragma unroll
                for (int p = 0; p < 8; ++p) {
                    int i2 = p * NTHR + tid; int k = i2 >> 6; int c = (i2 & 63) * 4;
                    wv[p] = *(const float4*)(w1g + (size_t)(k0 + k) * H1D + c);
                }
            }

            #pragma unroll
            for (int ks = 0; ks < 4; ++ks) {
                const int kk = ks * 8 + t;
                uint32_t af[4][4];
                #pragma unroll
                for (int mt = 0; mt < 4; ++mt) {
                    int r = wm * 64 + mt * 16 + g;
                    af[mt][0] = __float_as_uint(xs[r * XS_ST + kk]);
                    af[mt][1] = __float_as_uint(xs[(r + 8) * XS_ST + kk]);
                    af[mt][2] = __float_as_uint(xs[r * XS_ST + kk + 4]);
                    af[mt][3] = __float_as_uint(xs[(r + 8) * XS_ST + kk + 4]);
                }
                uint32_t bf[8][2];
                #pragma unroll
                for (int nt = 0; nt < 8; ++nt) {
                    int n = wn * 64 + nt * 8 + g;
                    bf[nt][0] = __float_as_uint(ws[kk * WS_ST + n]);
                    bf[nt][1] = __float_as_uint(ws[(kk + 4) * WS_ST + n]);
                }
                #pragma unroll
                for (int mt = 0; mt < 4; ++mt)
                    #pragma unroll
                    for (int nt = 0; nt < 8; ++nt)
                        mma8(acc1[mt][nt], af[mt], bf[nt]);
            }
        }

        // epilogue: bias + relu, tf32-round into smem h1
        const float* b1e = b1 + e * H1D;
        #pragma unroll
        for (int nt = 0; nt < 8; ++nt) {
            int c = wn * 64 + nt * 8 + 2 * t;
            float bb0 = b1e[c], bb1 = b1e[c + 1];
            #pragma unroll
            for (int mt = 0; mt < 4; ++mt) {
                int r = wm * 64 + mt * 16 + g;
                h1s[r * H1_ST + c]           = tf32r(fmaxf(acc1[mt][nt][0] + bb0, 0.f));
                h1s[r * H1_ST + c + 1]       = tf32r(fmaxf(acc1[mt][nt][1] + bb1, 0.f));
                h1s[(r + 8) * H1_ST + c]     = tf32r(fmaxf(acc1[mt][nt][2] + bb0, 0.f));
                h1s[(r + 8) * H1_ST + c + 1] = tf32r(fmaxf(acc1[mt][nt][3] + bb1, 0.f));
            }
        }
        if (tid < H2D) w3s[tid] = W3[e * H2D + tid];
        __syncthreads();

        // ================= GEMM2: h2 = relu(h1 @ W2[e] + b2[e]); eo = h2 . W3[e] =================
        float acc2[4][4][4];
        #pragma unroll
        for (int mt = 0; mt < 4; ++mt)
            #pragma unroll
            for (int nt = 0; nt < 4; ++nt)
                #pragma unroll
                for (int i = 0; i < 4; ++i) acc2[mt][nt][i] = 0.f;

        const float* w2g = W2 + (size_t)e * H1D * H2D;
        float4 wv2[4];
        #pragma unroll
        for (int p = 0; p < 4; ++p) {
            int i2 = p * NTHR + tid; int k = i2 >> 5; int c = (i2 & 31) * 4;
            wv2[p] = *(const float4*)(w2g + (size_t)k * H2D + c);
        }

        for (int kc = 0; kc < H1D / 32; ++kc) {
            __syncthreads();
            #pragma unroll
            for (int p = 0; p < 4; ++p) {
                int i2 = p * NTHR + tid; int k = i2 >> 5; int c = (i2 & 31) * 4;
                float4 v = wv2[p];
                v.x = tf32r(v.x); v.y = tf32r(v.y); v.z = tf32r(v.z); v.w = tf32r(v.w);
                *(float4*)(ws + k * W2_ST + c) = v;
            }
            __syncthreads();
            if (kc + 1 < H1D / 32) {
                int k0 = (kc + 1) * 32;
                #pragma unroll
                for (int p = 0; p < 4; ++p) {
                    int i2 = p * NTHR + tid; int k = i2 >> 5; int c = (i2 & 31) * 4;
                    wv2[p] = *(const float4*)(w2g + (size_t)(k0 + k) * H2D + c);
                }
            }
            #pragma unroll
            for (int ks = 0; ks < 4; ++ks) {
                const int kl = ks * 8 + t;
                const int kk = kc * 32 + kl;
                uint32_t af[4][4];
                #pragma unroll
                for (int mt = 0; mt < 4; ++mt) {
                    int r = wm * 64 + mt * 16 + g;
                    af[mt][0] = __float_as_uint(h1s[r * H1_ST + kk]);
                    af[mt][1] = __float_as_uint(h1s[(r + 8) * H1_ST + kk]);
                    af[mt][2] = __float_as_uint(h1s[r * H1_ST + kk + 4]);
                    af[mt][3] = __float_as_uint(h1s[(r + 8) * H1_ST + kk + 4]);
                }
                uint32_t bf[4][2];
                #pragma unroll
                for (int nt = 0; nt < 4; ++nt) {
                    int n = wn * 32 + nt * 8 + g;
                    bf[nt][0] = __float_as_uint(ws[kl * W2_ST + n]);
                    bf[nt][1] = __float_as_uint(ws[(kl + 4) * W2_ST + n]);
                }
                #pragma unroll
                for (int mt = 0; mt < 4; ++mt)
                    #pragma unroll
                    for (int nt = 0; nt < 4; ++nt)
                        mma8(acc2[mt][nt], af[mt], bf[nt]);
            }
        }

        // epilogue: relu + fold h2 . W3 directly from accumulators
        const float* b2e = b2 + e * H2D;
        float w30[4], w31[4], bb0[4], bb1[4];
        #pragma unroll
        for (int nt = 0; nt < 4; ++nt) {
            int c = wn * 32 + nt * 8 + 2 * t;
            w30[nt] = w3s[c];     w31[nt] = w3s[c + 1];
            bb0[nt] = b2e[c];     bb1[nt] = b2e[c + 1];
        }
        #pragma unroll
        for (int mt = 0; mt < 4; ++mt) {
            int r = wm * 64 + mt * 16 + g;
            float s0 = 0.f, s1 = 0.f;
            #pragma unroll
            for (int nt = 0; nt < 4; ++nt) {
                s0 += fmaxf(acc2[mt][nt][0] + bb0[nt], 0.f) * w30[nt]
                    + fmaxf(acc2[mt][nt][1] + bb1[nt], 0.f) * w31[nt];
                s1 += fmaxf(acc2[mt][nt][2] + bb0[nt], 0.f) * w30[nt]
                    + fmaxf(acc2[mt][nt][3] + bb1[nt], 0.f) * w31[nt];
            }
            s0 += __shfl_xor_sync(0xffffffffu, s0, 1);
            s0 += __shfl_xor_sync(0xffffffffu, s0, 2);
            s1 += __shfl_xor_sync(0xffffffffu, s1, 1);
            s1 += __shfl_xor_sync(0xffffffffu, s1, 2);
            if (t == 0) {
                eop[r * 4 + wn]       = s0;
                eop[(r + 8) * 4 + wn] = s1;
            }
        }
        __syncthreads();
        if (tid < BM) {
            eos[tid * NEXP + e] = eop[tid * 4 + 0] + eop[tid * 4 + 1]
                                + eop[tid * 4 + 2] + eop[tid * 4 + 3];
        }
    }
    __syncthreads();

    // ================= gate: softmax(x @ Wg + bg); predictions =================
    {
        int token = tid & 127, half = tid >> 7;
        const float* xrow = x + (size_t)(row0 + token) * IN_D + half * 640;
        const float* wg = Wg + (size_t)half * 640 * NEXP;
        float l[8];
        #pragma unroll
        for (int e2 = 0; e2 < 8; ++e2) l[e2] = 0.f;
        #pragma unroll 4
        for (int k = 0; k < 640; ++k) {
            float xv = xrow[k];
            float4 wa = *(const float4*)(wg + k * 8);
            float4 wb = *(const float4*)(wg + k * 8 + 4);
            l[0] += xv * wa.x; l[1] += xv * wa.y; l[2] += xv * wa.z; l[3] += xv * wa.w;
            l[4] += xv * wb.x; l[5] += xv * wb.y; l[6] += xv * wb.z; l[7] += xv * wb.w;
        }
        float* gp = h1s;  // reuse (free now)
        #pragma unroll
        for (int e2 = 0; e2 < 8; ++e2) gp[(token * 2 + half) * 8 + e2] = l[e2];
    }
    __syncthreads();
    if (tid < BM) {
        const float* gp = h1s;
        float lg[8];
        #pragma unroll
        for (int e2 = 0; e2 < 8; ++e2)
            lg[e2] = gp[tid * 16 + e2] + gp[tid * 16 + 8 + e2] + bg[e2];
        float m = lg[0];
        #pragma unroll
        for (int e2 = 1; e2 < 8; ++e2) m = fmaxf(m, lg[e2]);
        float pe[8], s = 0.f;
        #pragma unroll
        for (int e2 = 0; e2 < 8; ++e2) { pe[e2] = expf(lg[e2] - m); s += pe[e2]; }
        float inv = 1.0f / s;
        float pred = 0.f;
        #pragma unroll
        for (int e2 = 0; e2 < 8; ++e2) {
            float gv = pe[e2] * inv;
            pred += (eos[tid * NEXP + e2] + b3[e2]) * gv;
            if (write_gate) out[TOK_B + (size_t)(row0 + tid) * NEXP + e2] = gv;
        }
        out[row0 + tid] = pred;
    }
}

extern "C" void kernel_launch(void* const* d_in, const int* in_sizes, int n_in,
                              void* d_out, int out_size) {
    const float* x  = (const float*)d_in[0];
    const float* W1 = (const float*)d_in[1];
    const float* b1 = (const float*)d_in[2];
    const float* W2 = (const float*)d_in[3];
    const float* b2 = (const float*)d_in[4];
    const float* W3 = (const float*)d_in[5];
    const float* b3 = (const float*)d_in[6];
    const float* Wg = (const float*)d_in[7];
    const float* bg = (const float*)d_in[8];
    float* out = (float*)d_out;
    int write_gate = (out_size >= TOK_B * (NEXP + 1)) ? 1 : 0;

    cudaFuncSetAttribute(moe_fused, cudaFuncAttributeMaxDynamicSharedMemorySize, SM_BYTES);
    moe_fused<<<TOK_B / BM, NTHR, SM_BYTES>>>(x, W1, b1, W2, b2, W3, b3, Wg, bg, out, write_gate);
}